// round 1
// baseline (speedup 1.0000x reference)
#include <cuda_runtime.h>
#include <cuda_bf16.h>
#include <math_constants.h>

#define NPTS 16384
#define MCTR 4096
#define KNBR 32
#define FIN  64
#define RAD2 0.25f
#define MAXC 64          // candidate buffer per center (P(overflow) ~ 1e-30)

// ---------------- device scratch (no allocations allowed) ----------------
__device__ int   g_idx[MCTR];          // FPS sample indices
__device__ int   g_nbr[MCTR * KNBR];   // neighbor point indices
__device__ int   g_cnt[MCTR];          // neighbor counts (<= 32)

// ---------------- Stage 1: exact sequential FPS ----------------
// Single CTA, 1024 threads, 16 points per thread held in registers.
// Matches jnp.argmax first-index tie-break via (max value, min index).
__global__ __launch_bounds__(1024, 1)
void fps_kernel(const float* __restrict__ pos)
{
    __shared__ float s_c[3];
    __shared__ unsigned s_wv[32];
    __shared__ int s_wi[32];

    const int t = threadIdx.x;

    float px[16], py[16], pz[16], dmin[16];
    #pragma unroll
    for (int j = 0; j < 16; ++j) {
        int p = t + j * 1024;
        px[j] = pos[p * 3 + 0];
        py[j] = pos[p * 3 + 1];
        pz[j] = pos[p * 3 + 2];
        dmin[j] = CUDART_INF_F;
    }

    if (t == 0) {
        g_idx[0] = 0;
        s_c[0] = pos[0]; s_c[1] = pos[1]; s_c[2] = pos[2];
    }
    __syncthreads();

    for (int it = 1; it < MCTR; ++it) {
        const float cx = s_c[0], cy = s_c[1], cz = s_c[2];
        float bestv = -1.0f;
        int   besti = 0x7fffffff;
        #pragma unroll
        for (int j = 0; j < 16; ++j) {
            float dx = px[j] - cx, dy = py[j] - cy, dz = pz[j] - cz;
            // non-FMA, left-associated sum to mirror the reference rounding
            float d = __fadd_rn(__fadd_rn(__fmul_rn(dx, dx), __fmul_rn(dy, dy)),
                                __fmul_rn(dz, dz));
            float dm = fminf(dmin[j], d);
            dmin[j] = dm;
            if (dm > bestv) { bestv = dm; besti = t + j * 1024; }  // ascending idx -> first max
        }
        // warp argmax: max value (nonneg float bits are monotone as u32), then min index
        unsigned vb   = __float_as_uint(bestv);
        unsigned wmax = __reduce_max_sync(0xffffffffu, vb);
        int cand = (vb == wmax) ? besti : 0x7fffffff;
        int wmin = __reduce_min_sync(0xffffffffu, cand);
        if ((t & 31) == 0) { s_wv[t >> 5] = wmax; s_wi[t >> 5] = wmin; }
        __syncthreads();
        if (t < 32) {
            unsigned v = s_wv[t];
            int      i2 = s_wi[t];
            unsigned bmax = __reduce_max_sync(0xffffffffu, v);
            int c2 = (v == bmax) ? i2 : 0x7fffffff;
            int bi = __reduce_min_sync(0xffffffffu, c2);
            if (t == 0) {
                g_idx[it] = bi;
                s_c[0] = pos[bi * 3 + 0];
                s_c[1] = pos[bi * 3 + 1];
                s_c[2] = pos[bi * 3 + 2];
            }
        }
        __syncthreads();
    }
}

// ---------------- Stage 2: ball query (radius + rare nearest-32 selection) ----------------
// 512 blocks x 256 threads; 1 warp per center; pos tiled through smem.
#define CHUNK 2048
__global__ __launch_bounds__(256)
void nbr_kernel(const float* __restrict__ pos)
{
    __shared__ float sx[CHUNK], sy[CHUNK], sz[CHUNK];
    __shared__ int   s_ci[8][MAXC];
    __shared__ float s_cd[8][MAXC];

    const int tid  = threadIdx.x;
    const int w    = tid >> 5;
    const int lane = tid & 31;
    const int m    = blockIdx.x * 8 + w;

    const int cidx = g_idx[m];
    const float cx = pos[cidx * 3 + 0];
    const float cy = pos[cidx * 3 + 1];
    const float cz = pos[cidx * 3 + 2];

    int cnt = 0;
    for (int base = 0; base < NPTS; base += CHUNK) {
        __syncthreads();
        for (int i = tid; i < CHUNK; i += 256) {
            sx[i] = pos[(base + i) * 3 + 0];
            sy[i] = pos[(base + i) * 3 + 1];
            sz[i] = pos[(base + i) * 3 + 2];
        }
        __syncthreads();
        for (int i = lane; i < CHUNK; i += 32) {
            float dx = sx[i] - cx, dy = sy[i] - cy, dz = sz[i] - cz;
            float d2 = __fadd_rn(__fadd_rn(__fmul_rn(dx, dx), __fmul_rn(dy, dy)),
                                 __fmul_rn(dz, dz));
            bool in = (d2 <= RAD2);
            unsigned mk = __ballot_sync(0xffffffffu, in);
            int slot = cnt + __popc(mk & ((1u << lane) - 1u));
            if (in && slot < MAXC) { s_ci[w][slot] = base + i; s_cd[w][slot] = d2; }
            cnt += __popc(mk);
        }
    }
    cnt = min(cnt, MAXC);

    if (cnt <= KNBR) {
        if (lane < cnt) g_nbr[m * KNBR + lane] = s_ci[w][lane];
        if (lane == 0)  g_cnt[m] = cnt;
    } else {
        // exact nearest-32 (stable by index, matching lax.top_k tie behavior)
        for (int c = lane; c < cnt; c += 32) {
            float d = s_cd[w][c];
            int  ii = s_ci[w][c];
            int r = 0;
            for (int o = 0; o < cnt; ++o) {
                float d2o = s_cd[w][o];
                r += (d2o < d) || (d2o == d && s_ci[w][o] < ii);
            }
            if (r < KNBR) g_nbr[m * KNBR + r] = ii;
        }
        if (lane == 0) g_cnt[m] = KNBR;
    }
}

// ---------------- Stage 3: per-edge MLP + masked max aggregation ----------------
// One block (256 threads) per center; only real edges computed (cnt <= 32).
__global__ __launch_bounds__(256)
void mlp_kernel(const float* __restrict__ feat,
                const float* __restrict__ pos,
                const float* __restrict__ W1, const float* __restrict__ b1,
                const float* __restrict__ W2, const float* __restrict__ b2,
                const float* __restrict__ W3, const float* __restrict__ b3,
                float* __restrict__ out)
{
    __shared__ float xb[32][68];    // concat(x_j[64], rel[3])
    __shared__ float h1[32][64];
    __shared__ float h2[32][64];
    __shared__ float h3[32][128];

    const int m   = blockIdx.x;
    const int tid = threadIdx.x;
    const int w   = tid >> 5;
    const int lane = tid & 31;
    const int cnt = g_cnt[m];

    const int cidx = g_idx[m];
    const float cx = pos[cidx * 3 + 0];
    const float cy = pos[cidx * 3 + 1];
    const float cz = pos[cidx * 3 + 2];

    // stage neighbor inputs: warp per neighbor row
    for (int k = w; k < cnt; k += 8) {
        int j = g_nbr[m * KNBR + k];
        xb[k][lane]      = feat[j * FIN + lane];
        xb[k][lane + 32] = feat[j * FIN + lane + 32];
        if (lane == 0) {
            xb[k][64] = pos[j * 3 + 0] - cx;
            xb[k][65] = pos[j * 3 + 1] - cy;
            xb[k][66] = pos[j * 3 + 2] - cz;
        }
    }
    __syncthreads();

    // layer 1: [cnt,67] @ [67,64]
    for (int p = tid; p < cnt * 64; p += 256) {
        int k = p >> 6, o = p & 63;
        float acc = b1[o];
        #pragma unroll
        for (int i = 0; i < 67; ++i)
            acc = fmaf(xb[k][i], W1[i * 64 + o], acc);
        h1[k][o] = fmaxf(acc, 0.0f);
    }
    __syncthreads();

    // layer 2: [cnt,64] @ [64,64]
    for (int p = tid; p < cnt * 64; p += 256) {
        int k = p >> 6, o = p & 63;
        float acc = b2[o];
        #pragma unroll
        for (int i = 0; i < 64; ++i)
            acc = fmaf(h1[k][i], W2[i * 64 + o], acc);
        h2[k][o] = fmaxf(acc, 0.0f);
    }
    __syncthreads();

    // layer 3: [cnt,64] @ [64,128]
    for (int p = tid; p < cnt * 128; p += 256) {
        int k = p >> 7, o = p & 127;
        float acc = b3[o];
        #pragma unroll
        for (int i = 0; i < 64; ++i)
            acc = fmaf(h2[k][i], W3[i * 128 + o], acc);
        h3[k][o] = fmaxf(acc, 0.0f);
    }
    __syncthreads();

    // masked max over neighbors (cnt >= 1 always: center is its own neighbor)
    if (tid < 128) {
        float mx = -CUDART_INF_F;
        for (int k = 0; k < cnt; ++k) mx = fmaxf(mx, h3[k][tid]);
        out[m * 128 + tid] = mx;
    }
}

// ---------------- Stage 4: tail outputs pos[idx], batch[idx] ----------------
__global__ void tail_kernel(const float* __restrict__ pos, float* __restrict__ out,
                            int out_size)
{
    int m = blockIdx.x * blockDim.x + threadIdx.x;
    if (m >= MCTR) return;
    const int base = MCTR * 128;
    if (out_size >= base + 3 * MCTR) {
        int j = g_idx[m];
        out[base + 3 * m + 0] = pos[3 * j + 0];
        out[base + 3 * m + 1] = pos[3 * j + 1];
        out[base + 3 * m + 2] = pos[3 * j + 2];
    }
    if (out_size >= base + 3 * MCTR + MCTR) {
        out[base + 3 * MCTR + m] = 0.0f;   // batch is all zeros (same bits as int32 0)
    }
}

extern "C" void kernel_launch(void* const* d_in, const int* in_sizes, int n_in,
                              void* d_out, int out_size)
{
    const float* feat = (const float*)d_in[0];
    const float* pos  = (const float*)d_in[1];
    // d_in[2] = batch (all zeros, unused)
    const float* W1 = (const float*)d_in[3];
    const float* b1 = (const float*)d_in[4];
    const float* W2 = (const float*)d_in[5];
    const float* b2 = (const float*)d_in[6];
    const float* W3 = (const float*)d_in[7];
    const float* b3 = (const float*)d_in[8];
    float* out = (float*)d_out;

    fps_kernel<<<1, 1024>>>(pos);
    nbr_kernel<<<MCTR / 8, 256>>>(pos);
    mlp_kernel<<<MCTR, 256>>>(feat, pos, W1, b1, W2, b2, W3, b3, out);
    tail_kernel<<<(MCTR + 255) / 256, 256>>>(pos, out, out_size);
}